// round 3
// baseline (speedup 1.0000x reference)
#include <cuda_runtime.h>

// Deep-TEN encoding, fused FP32 kernel with packed f32x2 math (Blackwell FFMA2).
// B=64, N=4096, D=256, K=32. out = E [B,K,D] fp32.

#define Bb 64
#define Nn 4096
#define Dd 256
#define Kk 32
#define SPLIT 16
#define CHUNK (Nn / SPLIT)   // 256 points per block
#define TP 64                // points per smem tile
#define NTILES (CHUNK / TP)  // 4
#define CP 260               // C row pitch in floats
#define XP 260               // x row pitch in floats (XP*4 = 1040 B, 16B aligned)
#define WP 36                // w row pitch in floats
#define NTHR 256

typedef unsigned long long ull;

__device__ __forceinline__ ull fma2(ull a, ull b, ull c) {
    ull d; asm("fma.rn.f32x2 %0, %1, %2, %3;" : "=l"(d) : "l"(a), "l"(b), "l"(c)); return d;
}
__device__ __forceinline__ ull add2(ull a, ull b) {
    ull d; asm("add.rn.f32x2 %0, %1, %2;" : "=l"(d) : "l"(a), "l"(b)); return d;
}
__device__ __forceinline__ ull pack2(float lo, float hi) {
    ull d; asm("mov.b64 %0, {%1, %2};" : "=l"(d) : "f"(lo), "f"(hi)); return d;
}
__device__ __forceinline__ float2 unpack2(ull v) {
    float2 f; asm("mov.b64 {%0, %1}, %2;" : "=f"(f.x), "=f"(f.y) : "l"(v)); return f;
}

struct SmemLayout {
    float Cs[Kk * CP];    // 33280 B
    float xs[TP * XP];    // 66560 B
    float ws[TP * WP];    //  9216 B
    float part[NTHR];     //  1024 B
    float x2s[TP];
    float c2s[Kk];
    float Ss[Kk];
    float wsums[Kk];
};

__global__ __launch_bounds__(NTHR, 2)
void deepten_kernel(const float* __restrict__ x,
                    const float* __restrict__ Cg,
                    const float* __restrict__ Sg,
                    float* __restrict__ out)
{
    extern __shared__ unsigned char smem_raw[];
    SmemLayout* sm = reinterpret_cast<SmemLayout*>(smem_raw);

    const int tid  = threadIdx.x;
    const int warp = tid >> 5;
    const int lane = tid & 31;
    const int g    = lane >> 2;   // d-group 0..7   (phase A)
    const int kl   = lane & 3;    // k-lane  0..3   (phase A)
    const int kg   = warp & 3;    // k-octet        (phase B)
    const int half = warp >> 2;   // d-half         (phase B)
    const int b     = blockIdx.y;
    const int slice = blockIdx.x;

    // ---- stage C + S ----
    {
        const float4* C4 = reinterpret_cast<const float4*>(Cg);
        #pragma unroll
        for (int j = 0; j < 8; ++j) {
            int idx = tid + j * NTHR;
            int k = idx >> 6, dc = idx & 63;
            *reinterpret_cast<float4*>(&sm->Cs[k * CP + dc * 4]) = C4[idx];
        }
        if (tid < Kk) sm->Ss[tid] = Sg[tid];
    }
    __syncthreads();
    // ---- c2[k] ----
    {
        const float4* row = reinterpret_cast<const float4*>(&sm->Cs[lane * CP]);
        float s = 0.f;
        #pragma unroll
        for (int j = 0; j < 8; ++j) {
            float4 v = row[warp * 8 + j];
            s += v.x * v.x + v.y * v.y + v.z * v.z + v.w * v.w;
        }
        sm->part[tid] = s;
    }
    __syncthreads();
    if (tid < Kk) {
        float s = 0.f;
        #pragma unroll
        for (int q = 0; q < 8; ++q) s += sm->part[q * 32 + tid];
        sm->c2s[tid] = s;
    }
    __syncthreads();

    // ---- phase-A register-resident C: thread's k = warp*4+kl, d-subsegs t*8+g ----
    const int kA = warp * 4 + kl;
    ull cA[16];
    #pragma unroll
    for (int t = 0; t < 8; ++t) {
        ulonglong2 cv = *reinterpret_cast<const ulonglong2*>(&sm->Cs[kA * CP + (t * 8 + g) * 4]);
        cA[2 * t]     = cv.x;
        cA[2 * t + 1] = cv.y;
    }
    const float SkA  = sm->Ss[kA];
    const float c2A  = sm->c2s[kA];
    const float negS = -SkA, twoS = 2.f * SkA;

    // ---- phase-B accumulators: 8 k x 4 d per thread (packed) ----
    ull accB[8][2];
    #pragma unroll
    for (int j = 0; j < 8; ++j) { accB[j][0] = 0ull; accB[j][1] = 0ull; }
    float wacc = 0.f;

    const char* xpA = reinterpret_cast<const char*>(sm->xs) + g * 16;
    const char* xpB = reinterpret_cast<const char*>(sm->xs) + (half * 128 + lane * 4) * 4;

    for (int tile = 0; tile < NTILES; ++tile) {
        const int n0 = slice * CHUNK + tile * TP;
        __syncthreads();  // protect xs/ws reuse

        // ---- stage x tile (coalesced float4) ----
        {
            const float4* xg = reinterpret_cast<const float4*>(
                x + ((size_t)b * Nn + n0) * Dd);
            #pragma unroll
            for (int j = 0; j < 16; ++j) {
                int idx = tid + j * NTHR;
                int i = idx >> 6, dc = idx & 63;
                *reinterpret_cast<float4*>(&sm->xs[i * XP + dc * 4]) = xg[idx];
            }
        }
        __syncthreads();

        // ---- x2[i] via packed squares ----
        {
            int p = tid & 63, q = tid >> 6;
            const ulonglong2* row = reinterpret_cast<const ulonglong2*>(&sm->xs[p * XP + q * 64]);
            ull a0 = 0ull, a1 = 0ull;
            #pragma unroll
            for (int j = 0; j < 16; ++j) {
                ulonglong2 v = row[j];
                a0 = fma2(v.x, v.x, a0);
                a1 = fma2(v.y, v.y, a1);
            }
            float2 f = unpack2(add2(a0, a1));
            sm->part[tid] = f.x + f.y;
        }
        __syncthreads();
        if (tid < TP) {
            sm->x2s[tid] = sm->part[tid] + sm->part[tid + 64] +
                           sm->part[tid + 128] + sm->part[tid + 192];
        }
        __syncthreads();

        // ---- phase A: logits.  8 conflict-free 128B LDS + 16 FMA2 per point ----
        {
            #pragma unroll 2
            for (int i = 0; i < TP; ++i) {
                const ulonglong2* xr = reinterpret_cast<const ulonglong2*>(xpA + i * (XP * 4));
                ull a0 = 0ull, a1 = 0ull;
                #pragma unroll
                for (int t = 0; t < 8; ++t) {
                    ulonglong2 v = xr[t * 8];   // byte offset t*128 (compile-time)
                    a0 = fma2(v.x, cA[2 * t], a0);
                    a1 = fma2(v.y, cA[2 * t + 1], a1);
                }
                float2 f = unpack2(add2(a0, a1));
                float xc = f.x + f.y;
                xc += __shfl_xor_sync(0xffffffffu, xc, 4);
                xc += __shfl_xor_sync(0xffffffffu, xc, 8);
                xc += __shfl_xor_sync(0xffffffffu, xc, 16);
                float l = fmaf(twoS, xc, negS * (sm->x2s[i] + c2A));
                if (g == 0) sm->ws[i * WP + kA] = l;
            }
        }
        __syncthreads();

        // ---- softmax: warp handles 8 rows, lane = k ----
        {
            #pragma unroll
            for (int r = 0; r < 8; ++r) {
                int pg = warp * 8 + r;
                float l = sm->ws[pg * WP + lane];
                float m = l;
                #pragma unroll
                for (int off = 16; off; off >>= 1)
                    m = fmaxf(m, __shfl_xor_sync(0xffffffffu, m, off));
                float e = __expf(l - m);
                float s = e;
                #pragma unroll
                for (int off = 16; off; off >>= 1)
                    s += __shfl_xor_sync(0xffffffffu, s, off);
                sm->ws[pg * WP + lane] = __fdividef(e, s);
            }
        }
        __syncthreads();

        // ---- phase B: accB[k][d] += w[k] * x[d]  (16 FMA2 / point) ----
        {
            #pragma unroll 2
            for (int i = 0; i < TP; ++i) {
                float4 wv0 = *reinterpret_cast<const float4*>(&sm->ws[i * WP + kg * 8]);
                float4 wv1 = *reinterpret_cast<const float4*>(&sm->ws[i * WP + kg * 8 + 4]);
                ulonglong2 xv = *reinterpret_cast<const ulonglong2*>(xpB + i * (XP * 4));
                ull w0 = pack2(wv0.x, wv0.x);
                ull w1 = pack2(wv0.y, wv0.y);
                ull w2 = pack2(wv0.z, wv0.z);
                ull w3 = pack2(wv0.w, wv0.w);
                ull w4 = pack2(wv1.x, wv1.x);
                ull w5 = pack2(wv1.y, wv1.y);
                ull w6 = pack2(wv1.z, wv1.z);
                ull w7 = pack2(wv1.w, wv1.w);
                accB[0][0] = fma2(w0, xv.x, accB[0][0]); accB[0][1] = fma2(w0, xv.y, accB[0][1]);
                accB[1][0] = fma2(w1, xv.x, accB[1][0]); accB[1][1] = fma2(w1, xv.y, accB[1][1]);
                accB[2][0] = fma2(w2, xv.x, accB[2][0]); accB[2][1] = fma2(w2, xv.y, accB[2][1]);
                accB[3][0] = fma2(w3, xv.x, accB[3][0]); accB[3][1] = fma2(w3, xv.y, accB[3][1]);
                accB[4][0] = fma2(w4, xv.x, accB[4][0]); accB[4][1] = fma2(w4, xv.y, accB[4][1]);
                accB[5][0] = fma2(w5, xv.x, accB[5][0]); accB[5][1] = fma2(w5, xv.y, accB[5][1]);
                accB[6][0] = fma2(w6, xv.x, accB[6][0]); accB[6][1] = fma2(w6, xv.y, accB[6][1]);
                accB[7][0] = fma2(w7, xv.x, accB[7][0]); accB[7][1] = fma2(w7, xv.y, accB[7][1]);
            }
            // wsum partials: k = lane, rows warp*8..+7
            #pragma unroll
            for (int r = 0; r < 8; ++r)
                wacc += sm->ws[(warp * 8 + r) * WP + lane];
        }
    }

    // ---- reduce wsum across warps ----
    __syncthreads();
    sm->part[tid] = wacc;
    __syncthreads();
    if (tid < Kk) {
        float s = 0.f;
        #pragma unroll
        for (int q = 0; q < 8; ++q) s += sm->part[tid + 32 * q];
        sm->wsums[tid] = s;
    }
    __syncthreads();

    // ---- epilogue: E = accB - wsum*C, atomic combine across slices ----
    {
        float* outb = out + (size_t)b * (Kk * Dd);
        #pragma unroll
        for (int j = 0; j < 8; ++j) {
            int kk = kg * 8 + j;
            float wk = sm->wsums[kk];
            float4 c = *reinterpret_cast<const float4*>(&sm->Cs[kk * CP + half * 128 + lane * 4]);
            float2 a0 = unpack2(accB[j][0]);
            float2 a1 = unpack2(accB[j][1]);
            float* p = outb + kk * Dd + half * 128 + lane * 4;
            atomicAdd(p + 0, fmaf(-wk, c.x, a0.x));
            atomicAdd(p + 1, fmaf(-wk, c.y, a0.y));
            atomicAdd(p + 2, fmaf(-wk, c.z, a1.x));
            atomicAdd(p + 3, fmaf(-wk, c.w, a1.y));
        }
    }
}

extern "C" void kernel_launch(void* const* d_in, const int* in_sizes, int n_in,
                              void* d_out, int out_size)
{
    const float* x = (const float*)d_in[0];
    const float* C = (const float*)d_in[1];
    const float* S = (const float*)d_in[2];
    float* out = (float*)d_out;

    cudaFuncSetAttribute(deepten_kernel,
                         cudaFuncAttributeMaxDynamicSharedMemorySize,
                         (int)sizeof(SmemLayout));
    cudaMemsetAsync(d_out, 0, (size_t)out_size * sizeof(float));

    dim3 grid(SPLIT, Bb);
    deepten_kernel<<<grid, NTHR, sizeof(SmemLayout)>>>(x, C, S, out);
}

// round 5
// speedup vs baseline: 2.9918x; 2.9918x over previous
#include <cuda_runtime.h>
#include <cuda_bf16.h>

// Deep-TEN encoding via tensor cores (mma.sync bf16, 2-term split precision).
// B=64, N=4096, D=256, K=32. out = E [B,K,D] fp32.

#define Bb 64
#define Nn 4096
#define Dd 256
#define Kk 32
#define SPLIT 16
#define CHUNK (Nn / SPLIT)     // 256 points per block
#define TP 32                  // points per smem tile
#define NTILES (CHUNK / TP)    // 8
#define XPITCH 264             // bf16 elems per x row (528 B; 132 words % 32 == 4)
#define CPITCH 264
#define WPITCH 40              // bf16 elems per wt row (80 B, 16B-aligned rows)
#define XCP 36                 // xcbuf pitch (floats)
#define NTHR 256

struct Sm {
    __nv_bfloat16 xh[TP * XPITCH];
    __nv_bfloat16 xl[TP * XPITCH];
    __nv_bfloat16 Ch[Kk * CPITCH];
    __nv_bfloat16 Cl[Kk * CPITCH];
    __nv_bfloat16 wht[Kk * WPITCH];
    __nv_bfloat16 wlt[Kk * WPITCH];
    float xcbuf[TP * XCP];
    float x2s[TP], c2s[Kk], Ss[Kk], wsums[Kk];
    float part[NTHR];
};

__device__ __forceinline__ unsigned su32(const void* p) {
    return (unsigned)__cvta_generic_to_shared(p);
}
__device__ __forceinline__ void ldsm4(unsigned* r, unsigned addr) {
    asm volatile("ldmatrix.sync.aligned.m8n8.x4.shared.b16 {%0,%1,%2,%3}, [%4];"
                 : "=r"(r[0]), "=r"(r[1]), "=r"(r[2]), "=r"(r[3]) : "r"(addr));
}
__device__ __forceinline__ void ldsm2(unsigned* r, unsigned addr) {
    asm volatile("ldmatrix.sync.aligned.m8n8.x2.shared.b16 {%0,%1}, [%2];"
                 : "=r"(r[0]), "=r"(r[1]) : "r"(addr));
}
__device__ __forceinline__ void ldsm2t(unsigned* r, unsigned addr) {
    asm volatile("ldmatrix.sync.aligned.m8n8.x2.trans.shared.b16 {%0,%1}, [%2];"
                 : "=r"(r[0]), "=r"(r[1]) : "r"(addr));
}
__device__ __forceinline__ void mma16816(float* d, const unsigned* a, const unsigned* b) {
    asm("mma.sync.aligned.m16n8k16.row.col.f32.bf16.bf16.f32 "
        "{%0,%1,%2,%3}, {%4,%5,%6,%7}, {%8,%9}, {%0,%1,%2,%3};"
        : "+f"(d[0]), "+f"(d[1]), "+f"(d[2]), "+f"(d[3])
        : "r"(a[0]), "r"(a[1]), "r"(a[2]), "r"(a[3]), "r"(b[0]), "r"(b[1]));
}
// pack two f32 -> bf16x2 (lo goes to low 16 bits)
__device__ __forceinline__ unsigned packbf2(float hi, float lo) {
    unsigned r; asm("cvt.rn.bf16x2.f32 %0, %1, %2;" : "=r"(r) : "f"(hi), "f"(lo)); return r;
}

// Stage 4 fp32 values -> split bf16 hi/lo words, return sum of squares contribution
__device__ __forceinline__ float split4(float4 v, unsigned& h0, unsigned& h1,
                                        unsigned& l0, unsigned& l1) {
    h0 = packbf2(v.y, v.x);
    h1 = packbf2(v.w, v.z);
    float fx = __uint_as_float(h0 << 16);
    float fy = __uint_as_float(h0 & 0xffff0000u);
    float fz = __uint_as_float(h1 << 16);
    float fw = __uint_as_float(h1 & 0xffff0000u);
    l0 = packbf2(v.y - fy, v.x - fx);
    l1 = packbf2(v.w - fw, v.z - fz);
    return v.x * v.x + v.y * v.y + v.z * v.z + v.w * v.w;
}

__global__ __launch_bounds__(NTHR, 2)
void deepten_mma_kernel(const float* __restrict__ x,
                        const float* __restrict__ Cg,
                        const float* __restrict__ Sg,
                        float* __restrict__ out)
{
    extern __shared__ unsigned char smem_raw[];
    Sm* sm = reinterpret_cast<Sm*>(smem_raw);

    const int tid  = threadIdx.x;
    const int warp = tid >> 5;
    const int lane = tid & 31;
    const int b     = blockIdx.y;
    const int slice = blockIdx.x;

    // ---------------- stage C (split bf16) + c2 + S ----------------
    {
        #pragma unroll
        for (int p = 0; p < 4; ++p) {
            int row = warp * 4 + p;
            const float4* crow = reinterpret_cast<const float4*>(Cg + row * Dd);
            uint2* dsth = reinterpret_cast<uint2*>(sm->Ch + row * CPITCH);
            uint2* dstl = reinterpret_cast<uint2*>(sm->Cl + row * CPITCH);
            float sq = 0.f;
            #pragma unroll
            for (int s = 0; s < 2; ++s) {
                float4 v = crow[s * 32 + lane];
                unsigned h0, h1, l0, l1;
                sq += split4(v, h0, h1, l0, l1);
                dsth[s * 32 + lane] = make_uint2(h0, h1);
                dstl[s * 32 + lane] = make_uint2(l0, l1);
            }
            #pragma unroll
            for (int off = 16; off; off >>= 1)
                sq += __shfl_xor_sync(0xffffffffu, sq, off);
            if (lane == 0) sm->c2s[row] = sq;
        }
        if (tid < Kk) sm->Ss[tid] = Sg[tid];
    }

    // GEMM1 warp roles
    const int mi = warp & 1;        // point half (0-15 / 16-31)
    const int nj = warp >> 1;       // code slice (8 codes)
    // ldmatrix per-thread address components
    const int aRow = (lane & 7) + ((lane >> 3) & 1) * 8;   // row within 16
    const int aKo8 = (lane >> 4) * 8;                      // k offset (elems)
    const unsigned aoffX = (unsigned)((mi * 16 + aRow) * XPITCH + aKo8) * 2u;
    const unsigned boffC = (unsigned)((nj * 8 + (lane & 7)) * CPITCH + ((lane >> 3) & 1) * 8) * 2u;
    const unsigned aoffW = (unsigned)(aRow * WPITCH + aKo8) * 2u;
    const unsigned boffXt_row = (unsigned)aRow;            // point row within k-chunk

    const unsigned baseXh = su32(sm->xh), baseXl = su32(sm->xl);
    const unsigned baseCh = su32(sm->Ch), baseCl = su32(sm->Cl);
    const unsigned baseWh = su32(sm->wht), baseWl = su32(sm->wlt);

    // GEMM2 accumulators: 2 m-tiles (codes) x 4 n-tiles (d) per warp
    float e[2][4][4];
    #pragma unroll
    for (int m = 0; m < 2; ++m)
        #pragma unroll
        for (int n = 0; n < 4; ++n)
            #pragma unroll
            for (int q = 0; q < 4; ++q) e[m][n][q] = 0.f;
    float wacc = 0.f;

    for (int tile = 0; tile < NTILES; ++tile) {
        const int n0 = slice * CHUNK + tile * TP;
        __syncthreads();   // protect xh/xl/wt reuse from previous tile

        // ---- stage x tile (split bf16) + x2 ----
        #pragma unroll
        for (int p = 0; p < 4; ++p) {
            int row = warp * 4 + p;
            const float4* xrow = reinterpret_cast<const float4*>(
                x + ((size_t)b * Nn + n0 + row) * Dd);
            uint2* dsth = reinterpret_cast<uint2*>(sm->xh + row * XPITCH);
            uint2* dstl = reinterpret_cast<uint2*>(sm->xl + row * XPITCH);
            float sq = 0.f;
            #pragma unroll
            for (int s = 0; s < 2; ++s) {
                float4 v = xrow[s * 32 + lane];
                unsigned h0, h1, l0, l1;
                sq += split4(v, h0, h1, l0, l1);
                dsth[s * 32 + lane] = make_uint2(h0, h1);
                dstl[s * 32 + lane] = make_uint2(l0, l1);
            }
            #pragma unroll
            for (int off = 16; off; off >>= 1)
                sq += __shfl_xor_sync(0xffffffffu, sq, off);
            if (lane == 0) sm->x2s[row] = sq;
        }
        __syncthreads();

        // ---- GEMM1: xc[32pts, 32codes], 3 independent accumulators ----
        {
            float dhh[4] = {0.f, 0.f, 0.f, 0.f};
            float dhl[4] = {0.f, 0.f, 0.f, 0.f};
            float dlh[4] = {0.f, 0.f, 0.f, 0.f};
            #pragma unroll
            for (int ks = 0; ks < 16; ++ks) {
                unsigned ko = (unsigned)(ks * 32);   // bytes (16 bf16)
                unsigned ah[4], al[4], bh[2], bl[2];
                ldsm4(ah, baseXh + aoffX + ko);
                ldsm4(al, baseXl + aoffX + ko);
                ldsm2(bh, baseCh + boffC + ko);
                ldsm2(bl, baseCl + boffC + ko);
                mma16816(dhh, ah, bh);
                mma16816(dhl, ah, bl);
                mma16816(dlh, al, bh);
            }
            int r0 = mi * 16 + (lane >> 2);
            int c0 = nj * 8 + (lane & 3) * 2;
            float2 v0 = make_float2(dhh[0] + dhl[0] + dlh[0], dhh[1] + dhl[1] + dlh[1]);
            float2 v1 = make_float2(dhh[2] + dhl[2] + dlh[2], dhh[3] + dhl[3] + dlh[3]);
            *reinterpret_cast<float2*>(&sm->xcbuf[r0 * XCP + c0]) = v0;
            *reinterpret_cast<float2*>(&sm->xcbuf[(r0 + 8) * XCP + c0]) = v1;
        }
        __syncthreads();

        // ---- softmax: warp handles 4 points, lane = code ----
        {
            const float Sk = sm->Ss[lane];
            const float c2 = sm->c2s[lane];
            #pragma unroll
            for (int p = 0; p < 4; ++p) {
                int pt = warp * 4 + p;
                float xc = sm->xcbuf[pt * XCP + lane];
                float l = -Sk * (sm->x2s[pt] + c2 - 2.f * xc);
                float m = l;
                #pragma unroll
                for (int off = 16; off; off >>= 1)
                    m = fmaxf(m, __shfl_xor_sync(0xffffffffu, m, off));
                float ev = __expf(l - m);
                float s = ev;
                #pragma unroll
                for (int off = 16; off; off >>= 1)
                    s += __shfl_xor_sync(0xffffffffu, s, off);
                float w = __fdividef(ev, s);
                wacc += w;
                __nv_bfloat16 hb = __float2bfloat16(w);
                __nv_bfloat16 lb = __float2bfloat16(w - __bfloat162float(hb));
                sm->wht[lane * WPITCH + pt] = hb;
                sm->wlt[lane * WPITCH + pt] = lb;
            }
        }
        __syncthreads();

        // ---- GEMM2: E[codes, d-slice] += w^T x  (warp owns d = warp*32..+31) ----
        {
            #pragma unroll
            for (int ks = 0; ks < 2; ++ks) {
                unsigned k0e = (unsigned)(ks * 16);
                unsigned awh0[4], awl0[4], awh1[4], awl1[4];
                ldsm4(awh0, baseWh + aoffW + k0e * 2u);
                ldsm4(awl0, baseWl + aoffW + k0e * 2u);
                ldsm4(awh1, baseWh + aoffW + 16u * WPITCH * 2u + k0e * 2u);
                ldsm4(awl1, baseWl + aoffW + 16u * WPITCH * 2u + k0e * 2u);
                unsigned bX = (unsigned)((k0e + boffXt_row) * XPITCH + warp * 32) * 2u;
                #pragma unroll
                for (int nt = 0; nt < 4; ++nt) {
                    unsigned bxh[2], bxl[2];
                    ldsm2t(bxh, baseXh + bX + nt * 16u);
                    ldsm2t(bxl, baseXl + bX + nt * 16u);
                    mma16816(e[0][nt], awh0, bxh);
                    mma16816(e[0][nt], awh0, bxl);
                    mma16816(e[0][nt], awl0, bxh);
                    mma16816(e[1][nt], awh1, bxh);
                    mma16816(e[1][nt], awh1, bxl);
                    mma16816(e[1][nt], awl1, bxh);
                }
            }
        }
    }

    // ---------------- wsum reduction ----------------
    __syncthreads();
    sm->part[tid] = wacc;
    __syncthreads();
    if (tid < Kk) {
        float s = 0.f;
        #pragma unroll
        for (int q = 0; q < 8; ++q) s += sm->part[q * 32 + tid];
        sm->wsums[tid] = s;
    }
    __syncthreads();

    // ---------------- epilogue: E - wsum*C, atomic combine over slices ----------------
    {
        const int g = lane >> 2, t = lane & 3;
        float* outb = out + (size_t)b * (Kk * Dd);
        #pragma unroll
        for (int mt = 0; mt < 2; ++mt) {
            int k0 = mt * 16 + g;
            int k1 = k0 + 8;
            float w0 = sm->wsums[k0];
            float w1 = sm->wsums[k1];
            #pragma unroll
            for (int nt = 0; nt < 4; ++nt) {
                int d0 = warp * 32 + nt * 8 + 2 * t;
                const float* c0 = Cg + k0 * Dd + d0;
                const float* c1 = Cg + k1 * Dd + d0;
                float* o0 = outb + k0 * Dd + d0;
                float* o1 = outb + k1 * Dd + d0;
                atomicAdd(o0,     fmaf(-w0, __ldg(c0),     e[mt][nt][0]));
                atomicAdd(o0 + 1, fmaf(-w0, __ldg(c0 + 1), e[mt][nt][1]));
                atomicAdd(o1,     fmaf(-w1, __ldg(c1),     e[mt][nt][2]));
                atomicAdd(o1 + 1, fmaf(-w1, __ldg(c1 + 1), e[mt][nt][3]));
            }
        }
    }
}

extern "C" void kernel_launch(void* const* d_in, const int* in_sizes, int n_in,
                              void* d_out, int out_size)
{
    const float* x = (const float*)d_in[0];
    const float* C = (const float*)d_in[1];
    const float* S = (const float*)d_in[2];
    float* out = (float*)d_out;

    cudaFuncSetAttribute(deepten_mma_kernel,
                         cudaFuncAttributeMaxDynamicSharedMemorySize,
                         (int)sizeof(Sm));
    cudaMemsetAsync(d_out, 0, (size_t)out_size * sizeof(float));

    dim3 grid(SPLIT, Bb);
    deepten_mma_kernel<<<grid, NTHR, sizeof(Sm)>>>(x, C, S, out);
}